// round 11
// baseline (speedup 1.0000x reference)
#include <cuda_runtime.h>
#include <cuda_bf16.h>
#include <cstdint>
#include <cstddef>

// Problem constants
#define NB   8
#define CD   256
#define HWSZ 9216
#define TT   32
#define VV   256
#define TV   8192
#define NT   64                       // tiles per dim
#define NTILES (NT * (NT + 1) / 2)    // 2080 upper-tri tiles
#define NCTA 148
#define CHUNK_BASE (NTILES / NCTA)    // 14
#define CHUNK_EXTRA (NTILES - CHUNK_BASE * NCTA)  // 8
#define INV_TEMP 2.0f
#define SHIFT    2.0f

// GEMM tiling
#define TM 128
#define TN 128
#define PITCHB 528                    // 33*16B per SMEM tile row
#define TILE_BYTES (128 * PITCHB)     // 67584
#define STAGE_PITCH 129
#define OFF_B0 TILE_BYTES
#define OFF_B1 (2 * TILE_BYTES)
#define OFF_ROWNEG (3 * TILE_BYTES)
#define OFF_COLNEG (3 * TILE_BYTES + 512)
#define SMEM_TOTAL (3 * TILE_BYTES + 1024)   // 203776 bytes

// Scratch
__device__ __nv_bfloat16 g_Fb[(size_t)TV * CD];   // normalized feats, bf16 (4 MB)
__device__ float g_dot[(size_t)TV * TV];          // only same-label tiles written
__device__ float g_neg[TV];                       // per-row neg exp sums

// ---------------------------------------------------------------------------
__global__ void zero_kernel(float* out) {
    int i = blockIdx.x * blockDim.x + threadIdx.x;
    if (i < TV) g_neg[i] = 0.0f;
    if (i == 0) out[0] = 0.0f;
}

// ---------------------------------------------------------------------------
__global__ void gather_norm_kernel(const float* __restrict__ features,
                                   const int*   __restrict__ batch_inds,
                                   const int*   __restrict__ sample_inds)
{
    int i = blockIdx.x;
    int c = threadIdx.x;
    int b = batch_inds[i >> 8];
    int s = sample_inds[i];

    float x = features[((size_t)b * CD + c) * HWSZ + (size_t)s];

    __shared__ float red[256];
    red[c] = x * x;
    __syncthreads();
    #pragma unroll
    for (int ofs = 128; ofs > 0; ofs >>= 1) {
        if (c < ofs) red[c] += red[c + ofs];
        __syncthreads();
    }
    __shared__ float s_inv;
    if (c == 0) s_inv = 1.0f / fmaxf(sqrtf(red[0]), 1e-12f);
    __syncthreads();
    g_Fb[(size_t)i * CD + c] = __float2bfloat16(x * s_inv);
}

// ---------------------------------------------------------------------------
__device__ __forceinline__ uint32_t smem_u32(const void* p) {
    uint32_t a;
    asm("{ .reg .u64 t; cvta.to.shared.u64 t, %1; cvt.u32.u64 %0, t; }"
        : "=r"(a) : "l"(p));
    return a;
}

__device__ __forceinline__ void ldsm_x4(uint32_t* r, uint32_t addr) {
    asm volatile("ldmatrix.sync.aligned.m8n8.x4.shared.b16 {%0,%1,%2,%3}, [%4];"
                 : "=r"(r[0]), "=r"(r[1]), "=r"(r[2]), "=r"(r[3]) : "r"(addr));
}

__device__ __forceinline__ void mma16816(float* c, const uint32_t* a,
                                         uint32_t b0, uint32_t b1) {
    asm volatile(
        "mma.sync.aligned.m16n8k16.row.col.f32.bf16.bf16.f32 "
        "{%0,%1,%2,%3}, {%4,%5,%6,%7}, {%8,%9}, {%0,%1,%2,%3};"
        : "+f"(c[0]), "+f"(c[1]), "+f"(c[2]), "+f"(c[3])
        : "r"(a[0]), "r"(a[1]), "r"(a[2]), "r"(a[3]), "r"(b0), "r"(b1));
}

// async copy of a 128x256 bf16 tile into padded SMEM (one commit group by caller)
__device__ __forceinline__ void cp_tile(char* dst, int row0, int tid)
{
    #pragma unroll
    for (int it = 0; it < 16; it++) {
        int chunk = tid + it * 256;
        int r   = chunk >> 5;
        int c16 = chunk & 31;
        uint32_t da = smem_u32(dst + r * PITCHB + c16 * 16);
        const void* g = g_Fb + (size_t)(row0 + r) * CD + c16 * 8;
        asm volatile("cp.async.cg.shared.global [%0], [%1], 16;"
                     :: "r"(da), "l"(g));
    }
}
__device__ __forceinline__ void cp_commit() {
    asm volatile("cp.async.commit_group;" ::: "memory");
}
template <int N> __device__ __forceinline__ void cp_wait() {
    asm volatile("cp.async.wait_group %0;" :: "n"(N) : "memory");
}

// ---------------------------------------------------------------------------
// Kernel 2: persistent upper-triangular tile GEMM, fused SupCon-neg epilogue.
// Each CTA owns a contiguous strip-ordered chunk of tiles. A resident per
// strip; B double-buffered with cp.async.
// ---------------------------------------------------------------------------
__global__ __launch_bounds__(256)
void gram_fused_kernel(const int* __restrict__ labels)
{
    extern __shared__ char smem[];
    char*  At = smem;
    char*  B0 = smem + OFF_B0;
    char*  B1 = smem + OFF_B1;
    float* s_rowneg = (float*)(smem + OFF_ROWNEG);
    float* s_colneg = (float*)(smem + OFF_COLNEG);

    const int tid = threadIdx.x;
    const int wid = tid >> 5;
    const int lid = tid & 31;
    const int cta = blockIdx.x;

    const int start = cta * CHUNK_BASE + (cta < CHUNK_EXTRA ? cta : CHUNK_EXTRA);
    const int count = CHUNK_BASE + (cta < CHUNK_EXTRA ? 1 : 0);

    // decode first tile (strip-major upper-triangular)
    int rem = start, I = 0;
    #pragma unroll 1
    while (rem >= NT - I) { rem -= NT - I; I++; }
    int J = I + rem;

    // prologue: A of first strip + B of first tile
    cp_tile(At, I * TM, tid); cp_commit();
    cp_tile(B0, J * TN, tid); cp_commit();
    int cur_I = I;
    int buf = 0;

    const int wm = (wid & 3) * 32;
    const int wn = (wid >> 2) * 64;

    #pragma unroll 1
    for (int t = 0; t < count; t++) {
        const int i0 = I * TM;
        const int j0 = J * TN;
        const int la = labels[I >> 1];
        const int lb = labels[J >> 1];

        // A reload on strip change (prev iter fully synced; At free)
        if (I != cur_I) { cp_tile(At, i0, tid); cp_commit(); cur_I = I; }

        // decode + prefetch next B into the other buffer
        int In = I, Jn = J + 1;
        if (Jn == NT) { In = I + 1; Jn = In; }
        const bool have_next = (t + 1 < count);
        char* Bcur  = buf ? B1 : B0;
        char* Bnext = buf ? B0 : B1;
        if (have_next) { cp_tile(Bnext, Jn * TN, tid); cp_commit(); }

        // retire everything except the next-B prefetch
        if (have_next) cp_wait<1>(); else cp_wait<0>();
        __syncthreads();

        if (tid < 128) { s_rowneg[tid] = 0.0f; s_colneg[tid] = 0.0f; }

        const uint32_t a_base = smem_u32(At)   + (wm + (lid & 15)) * PITCHB + (lid >> 4) * 16;
        const uint32_t b_base = smem_u32(Bcur) + (wn + (lid & 15)) * PITCHB + (lid >> 4) * 16;

        float acc[2][8][4];
        #pragma unroll
        for (int mi = 0; mi < 2; mi++)
            #pragma unroll
            for (int nj = 0; nj < 8; nj++)
                #pragma unroll
                for (int q = 0; q < 4; q++) acc[mi][nj][q] = 0.0f;

        #pragma unroll
        for (int ks = 0; ks < 16; ks++) {
            const int kb = ks * 32;
            uint32_t a[2][4], b[4][4];
            #pragma unroll
            for (int mi = 0; mi < 2; mi++)
                ldsm_x4(a[mi], a_base + mi * 16 * PITCHB + kb);
            #pragma unroll
            for (int nb = 0; nb < 4; nb++)
                ldsm_x4(b[nb], b_base + nb * 16 * PITCHB + kb);
            #pragma unroll
            for (int mi = 0; mi < 2; mi++)
                #pragma unroll
                for (int nj = 0; nj < 8; nj++)
                    mma16816(acc[mi][nj], a[mi],
                             b[nj >> 1][nj & 1], b[nj >> 1][2 + (nj & 1)]);
        }

        if (la != lb) {
            // ---- negative tile: exp row/col sums ----
            float cs0[8], cs1[8];
            #pragma unroll
            for (int nj = 0; nj < 8; nj++) { cs0[nj] = 0.0f; cs1[nj] = 0.0f; }
            __syncthreads();   // s_rowneg/s_colneg zeroing visible

            #pragma unroll
            for (int mi = 0; mi < 2; mi++) {
                float rs0 = 0.0f, rs1 = 0.0f;
                #pragma unroll
                for (int nj = 0; nj < 8; nj++) {
                    float e0 = __expf(INV_TEMP * acc[mi][nj][0] - SHIFT);
                    float e1 = __expf(INV_TEMP * acc[mi][nj][1] - SHIFT);
                    float e2 = __expf(INV_TEMP * acc[mi][nj][2] - SHIFT);
                    float e3 = __expf(INV_TEMP * acc[mi][nj][3] - SHIFT);
                    rs0 += e0 + e1;  rs1 += e2 + e3;
                    cs0[nj] += e0 + e2;  cs1[nj] += e1 + e3;
                }
                rs0 += __shfl_xor_sync(0xffffffffu, rs0, 1);
                rs0 += __shfl_xor_sync(0xffffffffu, rs0, 2);
                rs1 += __shfl_xor_sync(0xffffffffu, rs1, 1);
                rs1 += __shfl_xor_sync(0xffffffffu, rs1, 2);
                if ((lid & 3) == 0) {
                    atomicAdd(&s_rowneg[wm + mi * 16 + (lid >> 2)],     rs0);
                    atomicAdd(&s_rowneg[wm + mi * 16 + (lid >> 2) + 8], rs1);
                }
            }
            #pragma unroll
            for (int nj = 0; nj < 8; nj++) {
                float v0 = cs0[nj], v1 = cs1[nj];
                v0 += __shfl_xor_sync(0xffffffffu, v0, 4);
                v0 += __shfl_xor_sync(0xffffffffu, v0, 8);
                v0 += __shfl_xor_sync(0xffffffffu, v0, 16);
                v1 += __shfl_xor_sync(0xffffffffu, v1, 4);
                v1 += __shfl_xor_sync(0xffffffffu, v1, 8);
                v1 += __shfl_xor_sync(0xffffffffu, v1, 16);
                if (lid < 4) {
                    atomicAdd(&s_colneg[wn + nj * 8 + lid * 2],     v0);
                    atomicAdd(&s_colneg[wn + nj * 8 + lid * 2 + 1], v1);
                }
            }
            __syncthreads();
            if (tid < 128)  atomicAdd(&g_neg[i0 + tid],       s_rowneg[tid]);
            else            atomicAdd(&g_neg[j0 + tid - 128], s_colneg[tid - 128]);
        } else {
            // ---- positive tile: materialize in g_dot ----
            #pragma unroll
            for (int mi = 0; mi < 2; mi++) {
                #pragma unroll
                for (int nj = 0; nj < 8; nj++) {
                    int r = i0 + wm + mi * 16 + (lid >> 2);
                    int c = j0 + wn + nj * 8 + (lid & 3) * 2;
                    float2 v0 = make_float2(INV_TEMP * acc[mi][nj][0],
                                            INV_TEMP * acc[mi][nj][1]);
                    float2 v1 = make_float2(INV_TEMP * acc[mi][nj][2],
                                            INV_TEMP * acc[mi][nj][3]);
                    *(float2*)&g_dot[(size_t)r * TV + c]       = v0;
                    *(float2*)&g_dot[(size_t)(r + 8) * TV + c] = v1;
                }
            }
            if (I != J) {
                // transpose via the now-consumed current B buffer
                __syncthreads();
                float* stage = (float*)Bcur;
                #pragma unroll
                for (int mi = 0; mi < 2; mi++) {
                    #pragma unroll
                    for (int nj = 0; nj < 8; nj++) {
                        int r = wm + mi * 16 + (lid >> 2);
                        int c = wn + nj * 8 + (lid & 3) * 2;
                        stage[r * STAGE_PITCH + c]           = INV_TEMP * acc[mi][nj][0];
                        stage[r * STAGE_PITCH + c + 1]       = INV_TEMP * acc[mi][nj][1];
                        stage[(r + 8) * STAGE_PITCH + c]     = INV_TEMP * acc[mi][nj][2];
                        stage[(r + 8) * STAGE_PITCH + c + 1] = INV_TEMP * acc[mi][nj][3];
                    }
                }
                __syncthreads();
                float* dstT = &g_dot[(size_t)j0 * TV + i0];
                #pragma unroll 4
                for (int idx = tid; idx < TM * TN; idx += 256) {
                    int r = idx & 127;
                    int c = idx >> 7;
                    dstT[(size_t)c * TV + r] = stage[r * STAGE_PITCH + c];
                }
            }
        }

        __syncthreads();   // all epilogue use of Bcur done before it becomes prefetch target
        buf ^= 1;
        I = In; J = Jn;
    }
}

// ---------------------------------------------------------------------------
// Kernel 3: positive pass (fast log).
// ---------------------------------------------------------------------------
__global__ __launch_bounds__(256) void pospass_kernel(const int* __restrict__ labels,
                                                      float* __restrict__ out)
{
    __shared__ int   labs[TT];
    __shared__ float red[256];

    const int tid = threadIdx.x;
    const int i   = blockIdx.x;
    if (tid < TT) labs[tid] = labels[tid];
    __syncthreads();

    const int li   = labs[i >> 8];
    const float ng = g_neg[i];
    const float* row = g_dot + (size_t)i * TV;

    float psum = 0.0f;
    int   pcnt = 0;
    #pragma unroll 1
    for (int t = 0; t < TT; t++) {
        if (labs[t] != li) continue;
        int j = t * VV + tid;
        float d = row[j];
        if (j != i) {
            float l = d - SHIFT;
            psum += l - __logf(__expf(l) + ng);
            pcnt++;
        }
    }

    red[tid] = psum;
    __syncthreads();
    #pragma unroll
    for (int ofs = 128; ofs > 0; ofs >>= 1) {
        if (tid < ofs) red[tid] += red[tid + ofs];
        __syncthreads();
    }
    float psum_tot = red[0];
    __syncthreads();
    red[tid] = (float)pcnt;
    __syncthreads();
    #pragma unroll
    for (int ofs = 128; ofs > 0; ofs >>= 1) {
        if (tid < ofs) red[tid] += red[tid + ofs];
        __syncthreads();
    }
    if (tid == 0) {
        float pcnt_tot = red[0];
        float mean_lp  = psum_tot / fmaxf(pcnt_tot, 1e-10f);
        atomicAdd(out, -mean_lp / (float)TV);
    }
}

// ---------------------------------------------------------------------------
extern "C" void kernel_launch(void* const* d_in, const int* in_sizes, int n_in,
                              void* d_out, int out_size)
{
    const float* features    = (const float*)d_in[0];
    const int*   batch_inds  = (const int*)d_in[1];
    const int*   sample_inds = (const int*)d_in[2];
    const int*   labels      = (const int*)d_in[3];
    float*       out         = (float*)d_out;

    cudaFuncSetAttribute(gram_fused_kernel,
                         cudaFuncAttributeMaxDynamicSharedMemorySize, SMEM_TOTAL);

    zero_kernel<<<TV / 256, 256>>>(out);
    gather_norm_kernel<<<TV, 256>>>(features, batch_inds, sample_inds);
    gram_fused_kernel<<<NCTA, 256, SMEM_TOTAL>>>(labels);
    pospass_kernel<<<TV, 256>>>(labels, out);
}